// round 13
// baseline (speedup 1.0000x reference)
#include <cuda_runtime.h>
#include <cstdint>

// Spiking-neuron forward scan, K=16 steps, collapsed to a two-value lookup.
//
// z_t = ((v-T)/(|v|+1) > 0) == (v > T) since denom >= 1. Given the spike
// pattern, out = sum z_t*d_t is a constant. Pattern is a function of v0=|x|.
// Induction: if the pattern agrees at both ends of an interval, the prefix
// constant C makes each step's compare (v0 - C > T_t) monotone in v0, so the
// pattern is uniform on the interval.
//
// Builder: per 2^-11 cell, if endpoint patterns agree -> clean {INF, o, o}.
// Else bisect the transition b (on float bits, exact scans), verify both
// sub-intervals by endpoint agreement -> {b, oLo, oHi} (exact). Verification
// failure (>=2 transitions in cell, rare) -> {0, NaN, NaN} -> exact fallback.
// Main kernel: idx = (int)(v0*2048) exact; val = v0 > brk ? hi : lo; fallback
// grouped per 8 elements behind a ballot so divergence cost ~0.

#define NCELL 2048

#define H_LIST {-0.00285825f, 0.09859432f, 0.07954306f, 0.08560576f, 0.0910411f, 0.10557652f, \
                0.04608637f, 0.07096123f, 0.01989892f, 0.03412642f, 0.03321506f, 0.01300904f, \
                -0.02348068f, 0.06102338f, -0.00509757f, 0.00051896f}
#define D_LIST {0.04908372f, -0.00948576f, 0.00083943f, 0.07961489f, 0.08128168f, 0.02395899f, \
                0.05197346f, 0.01595683f, 0.02185501f, 0.01893722f, 0.0074682f, -0.00088913f, \
                0.01660369f, 0.00298292f, 0.0071363f, 0.00279426f}
#define T_LIST {0.20153396f, -0.01304637f, -0.19541621f, 0.19903184f, 0.1529713f, -0.00479887f, \
                0.07102165f, 0.02109929f, 0.01368383f, -0.00360851f, -0.01454873f, -0.03991705f, \
                -0.00440092f, -0.06122432f, -0.02989412f, -0.04975629f}

__device__ __align__(16) float4 g_cells[NCELL];

// Exact scan, reference op order. 'one' == 1.0f runtime param keeps FFMA form.
static __device__ __forceinline__ float snn_scan(float v0, float one) {
    constexpr float Hc[16] = H_LIST;
    constexpr float Dc[16] = D_LIST;
    constexpr float Tc[16] = T_LIST;
    float v = v0, o = 0.0f;
#pragma unroll
    for (int t = 0; t < 15; t++) {
        if (v > Tc[t]) {
            o = fmaf(one, Dc[t], o);
            v = fmaf(one, -Hc[t + 1], v);
        }
    }
    if (v > Tc[15]) o = fmaf(one, Dc[15], o);
    return o;
}

// Exact scan returning the 16-bit spike pattern and output value.
static __device__ __forceinline__ uint32_t snn_pat(float v0, float one, float* oOut) {
    constexpr float Hc[16] = H_LIST;
    constexpr float Dc[16] = D_LIST;
    constexpr float Tc[16] = T_LIST;
    float v = v0, o = 0.0f;
    uint32_t pat = 0;
#pragma unroll
    for (int t = 0; t < 16; t++) {
        bool z = v > Tc[t];
        pat |= (uint32_t)z << t;
        if (z) {
            o = fmaf(one, Dc[t], o);
            if (t < 15) v = fmaf(one, -Hc[t + 1], v);
        }
    }
    *oOut = o;
    return pat;
}

__global__ void build_table(float one) {
    int k = blockIdx.x * blockDim.x + threadIdx.x;
    if (k >= NCELL) return;

    float lo = (float)k * 0x1p-11f;  // exact
    float hi;
    if (k == NCELL - 1) {
        hi = 3.0e38f;  // top cell extends upward (clamped idx)
    } else {
        float e = (float)(k + 1) * 0x1p-11f;
        hi = __int_as_float(__float_as_int(e) - 1);  // nextdown
    }

    float oLo, oHi;
    uint32_t pl = snn_pat(lo, one, &oLo);
    uint32_t ph = snn_pat(hi, one, &oHi);

    float4 cell;
    if (pl == ph) {
        // Uniform cell (endpoint agreement + monotone induction).
        cell = make_float4(__int_as_float(0x7F800000), oLo, oLo, 0.0f);  // brk=+INF
    } else {
        // Bisect on positive-float bit order for the transition point.
        uint32_t a = __float_as_uint(lo), c = __float_as_uint(hi);
        while (c - a > 1u) {
            uint32_t m = a + (c - a) / 2u;
            float om;
            uint32_t pm = snn_pat(__uint_as_float(m), one, &om);
            if (pm == pl) a = m; else c = m;
        }
        float b = __uint_as_float(a), bp = __uint_as_float(c);
        float ob, obp;
        uint32_t pb = snn_pat(b, one, &ob);
        uint32_t pbp = snn_pat(bp, one, &obp);
        if (pb == pl && pbp == ph) {
            // [lo,b] uniform (== oLo), (b,hi] uniform (== oHi): exact split.
            cell = make_float4(b, oLo, oHi, 0.0f);
        } else {
            // >=2 transitions: mark dirty (both values NaN -> always caught).
            float qnan = __int_as_float(0x7FC00000);
            cell = make_float4(0.0f, qnan, qnan, 0.0f);
        }
    }
    g_cells[k] = cell;
}

static __device__ __forceinline__ float lut_val(float xv, const float4* tbl, bool* bad) {
    float v0 = fabsf(xv);
    int idx = (int)(v0 * 2048.0f);   // exact (power-of-two scale)
    idx = min(idx, NCELL - 1);
    float4 c = tbl[idx];
    float val = (v0 > c.x) ? c.z : c.y;
    *bad |= !(val == val);
    return val;
}

static __device__ __forceinline__ float finish(float xv, float val) {
    // out = val * sign(x): XOR sign bit; exact 0 for x == 0.
    uint32_t rb = __float_as_uint(val) ^ (__float_as_uint(xv) & 0x80000000u);
    return (xv == 0.0f) ? 0.0f : __uint_as_float(rb);
}

__global__ void __launch_bounds__(256) Squre02_kernel(const float* __restrict__ x,
                                                      float* __restrict__ y, int n,
                                                      float one) {
    __shared__ __align__(16) float4 tbl[NCELL];
    {
#pragma unroll
        for (int i = threadIdx.x; i < NCELL; i += 256) tbl[i] = g_cells[i];
    }
    __syncthreads();

    const int tid = blockIdx.x * blockDim.x + threadIdx.x;
    const int nthreads = gridDim.x * blockDim.x;
    const int n4 = n >> 2;
    const float4* __restrict__ x4 = (const float4*)x;
    float4* __restrict__ y4 = (float4*)y;

    for (int i = tid; i < n4; i += 2 * nthreads) {
        const int i2 = i + nthreads;
        const bool has2 = (i2 < n4);
        float4 a = __ldcs(&x4[i]);
        float4 b = has2 ? __ldcs(&x4[i2]) : make_float4(0.f, 0.f, 0.f, 0.f);

        bool bad = false;
        float va0 = lut_val(a.x, tbl, &bad);
        float va1 = lut_val(a.y, tbl, &bad);
        float va2 = lut_val(a.z, tbl, &bad);
        float va3 = lut_val(a.w, tbl, &bad);
        float vb0 = lut_val(b.x, tbl, &bad);
        float vb1 = lut_val(b.y, tbl, &bad);
        float vb2 = lut_val(b.z, tbl, &bad);
        float vb3 = lut_val(b.w, tbl, &bad);

        // Grouped rare fallback: one branch region per 8 elements.
        if (__ballot_sync(__activemask(), bad)) {
            if (!(va0 == va0)) va0 = snn_scan(fabsf(a.x), one);
            if (!(va1 == va1)) va1 = snn_scan(fabsf(a.y), one);
            if (!(va2 == va2)) va2 = snn_scan(fabsf(a.z), one);
            if (!(va3 == va3)) va3 = snn_scan(fabsf(a.w), one);
            if (!(vb0 == vb0)) vb0 = snn_scan(fabsf(b.x), one);
            if (!(vb1 == vb1)) vb1 = snn_scan(fabsf(b.y), one);
            if (!(vb2 == vb2)) vb2 = snn_scan(fabsf(b.z), one);
            if (!(vb3 == vb3)) vb3 = snn_scan(fabsf(b.w), one);
        }

        float4 ra, rb;
        ra.x = finish(a.x, va0);
        ra.y = finish(a.y, va1);
        ra.z = finish(a.z, va2);
        ra.w = finish(a.w, va3);
        rb.x = finish(b.x, vb0);
        rb.y = finish(b.y, vb1);
        rb.z = finish(b.z, vb2);
        rb.w = finish(b.w, vb3);

        __stcs(&y4[i], ra);
        if (has2) __stcs(&y4[i2], rb);
    }

    // Scalar tail (not hit for this shape).
    for (int j = (n4 << 2) + tid; j < n; j += nthreads) {
        bool bad = false;
        float v = lut_val(x[j], tbl, &bad);
        if (!(v == v)) v = snn_scan(fabsf(x[j]), one);
        y[j] = finish(x[j], v);
    }
}

extern "C" void kernel_launch(void* const* d_in, const int* in_sizes, int n_in,
                              void* d_out, int out_size) {
    const float* x = (const float*)d_in[0];
    for (int i = 0; i < n_in; i++) {
        if (in_sizes[i] == out_size) { x = (const float*)d_in[i]; break; }
    }
    float* y = (float*)d_out;
    const int n = out_size;

    build_table<<<NCELL / 256, 256>>>(1.0f);
    // 148 SMs x 7 CTAs (smem 32KB/CTA -> 7 resident): balanced grid-stride.
    Squre02_kernel<<<1036, 256>>>(x, y, n, 1.0f);
}